// round 17
// baseline (speedup 1.0000x reference)
#include <cuda_runtime.h>

// topk_mean (k=2) segment pooling.
// h: [BS, SEQ, EMB] fp32, patch_ids: [BS, SEQ] int32 sorted ascending per batch.
// out: [BS, PNUM, EMB] fp32.
// Semantics (faithful to reference tie-masking loop):
//   max1 = segment max; max2 = max over values strictly != max1 (or -1e9 if none)
//   count==0 -> 0 ; count==1 -> max1 ; count>=2 -> (max1 + max2)/2

#define BS    8
#define SEQ   4096
#define EMB   512
#define PNUM  1024
#define EV4   (EMB / 4)         /* 128 float4 per row */
#define NPATCH (BS * PNUM)      /* 8192 flattened (b,p) */
#define GRID_X (16 * 148)       /* full residency: 16 blocks/SM on 148 SMs */
#define NEG_INF_V (-1.0e9f)

// bounds[b*PNUM+p] = {start, end}: token range of patch p (patch_ids sorted).
__device__ int2 g_bounds[NPATCH];

__global__ void starts_kernel(const int* __restrict__ pid) {
    const int b = blockIdx.y;
    const int t = blockIdx.x * blockDim.x + threadIdx.x;
    if (t >= SEQ) return;
    const int* __restrict__ p = pid + b * SEQ;
    int2* __restrict__ bd = g_bounds + b * PNUM;

    const int cur  = p[t];
    const int prev = (t == 0) ? -1 : p[t - 1];
    for (int q = prev + 1; q <= cur; ++q) {
        bd[q].x = t;
        if (q >= 1) bd[q - 1].y = t;
    }
    if (t == SEQ - 1) {
        for (int q = cur + 1; q <= PNUM; ++q) {
            if (q < PNUM) bd[q].x = SEQ;
            bd[q - 1].y = SEQ;
        }
    }
}

// Running top-2 with tie-skip: v == m1 leaves m2 unchanged (select form).
__device__ __forceinline__ void upd1(float v, float& m1, float& m2) {
    const float nm2 = (v > m1) ? m1 : ((v < m1) ? fmaxf(m2, v) : m2);
    m1 = fmaxf(m1, v);
    m2 = nm2;
}
__device__ __forceinline__ void upd4(const float4 v, float4& m1, float4& m2) {
    upd1(v.x, m1.x, m2.x);
    upd1(v.y, m1.y, m2.y);
    upd1(v.z, m1.z, m2.z);
    upd1(v.w, m1.w, m2.w);
}

// Persistent grid-stride: each CTA handles patches idx, idx+GRID_X, ...
// The next patch's bounds load issues BEFORE the current patch's token loop,
// hiding the dependent-load prefix for every patch after the first.
__global__ __launch_bounds__(128)
void pool_kernel(const float4* __restrict__ h4, float4* __restrict__ out4) {
    const int tid    = threadIdx.x;
    const int stride = gridDim.x;

    int idx = blockIdx.x;
    int2 be = g_bounds[idx];

    for (;;) {
        const int nidx = idx + stride;
        int2 beN;
        if (nidx < NPATCH) beN = g_bounds[nidx];   // prefetch next bounds

        // ---- process patch idx (b = idx/PNUM is folded into row math) ----
        const int cnt = be.y - be.x;
        float4* __restrict__ o = out4 + (size_t)idx * EV4 + tid;

        if (cnt == 0) {
            *o = make_float4(0.f, 0.f, 0.f, 0.f);
        } else {
            // token rows: batch b's rows start at b*SEQ; idx>>10 == b
            const float4* __restrict__ hb =
                h4 + (((size_t)(idx >> 10) * SEQ) + be.x) * EV4 + tid;

            float4 m1 = hb[0];
            if (cnt == 1) {
                *o = m1;
            } else {
                float4 m2 = make_float4(-INFINITY, -INFINITY, -INFINITY, -INFINITY);
                for (int t = 1; t < cnt; ++t)
                    upd4(hb[(size_t)t * EV4], m1, m2);

                float4 r;
                r.x = 0.5f * (m1.x + ((m2.x == -INFINITY) ? NEG_INF_V : m2.x));
                r.y = 0.5f * (m1.y + ((m2.y == -INFINITY) ? NEG_INF_V : m2.y));
                r.z = 0.5f * (m1.z + ((m2.z == -INFINITY) ? NEG_INF_V : m2.z));
                r.w = 0.5f * (m1.w + ((m2.w == -INFINITY) ? NEG_INF_V : m2.w));
                *o = r;
            }
        }
        // ------------------------------------------------------------------

        if (nidx >= NPATCH) break;
        idx = nidx;
        be  = beN;
    }
}

extern "C" void kernel_launch(void* const* d_in, const int* in_sizes, int n_in,
                              void* d_out, int out_size) {
    const float* h   = (const float*)d_in[0];
    const int*   pid = (const int*)d_in[1];
    float*       out = (float*)d_out;

    (void)in_sizes; (void)n_in; (void)out_size;

    dim3 g1((SEQ + 255) / 256, BS);
    starts_kernel<<<g1, 256>>>(pid);

    pool_kernel<<<GRID_X, 128>>>((const float4*)h, (float4*)out);
}